// round 1
// baseline (speedup 1.0000x reference)
#include <cuda_runtime.h>
#include <cstdint>

// ---------------- constants ----------------
#define CCH   48
#define HID   256
#define HWD   256
#define BN    8
#define KTOT  144
#define NPIXTOT (BN*HWD*HWD)   // 524288

// ---------------- device scratch (no runtime allocation allowed) ----------------
__device__ float g_xbuf[(size_t)BN * HWD * HWD * CCH];   // ping-pong x buffer (~100MB)
__device__ float g_w1t[KTOT * HID];                      // w1 transposed: [k][o]
__device__ float g_w2t[HID * CCH];                       // w2 transposed: [o][c]

// ---------------- threefry2x32 (exact JAX semantics, 20 rounds) ----------------
__host__ __device__ __forceinline__ void threefry2x32(
    uint32_t k0, uint32_t k1, uint32_t x0, uint32_t x1,
    uint32_t& o0, uint32_t& o1)
{
  uint32_t ks2 = k0 ^ k1 ^ 0x1BD11BDAu;
  uint32_t v0 = x0 + k0, v1 = x1 + k1;
#define TF_ROTL(v, r) (((v) << (r)) | ((v) >> (32 - (r))))
#define TF_RND(r) { v0 += v1; v1 = TF_ROTL(v1, r); v1 ^= v0; }
  TF_RND(13) TF_RND(15) TF_RND(26) TF_RND(6)
  v0 += k1;  v1 += ks2 + 1u;
  TF_RND(17) TF_RND(29) TF_RND(16) TF_RND(24)
  v0 += ks2; v1 += k0 + 2u;
  TF_RND(13) TF_RND(15) TF_RND(26) TF_RND(6)
  v0 += k0;  v1 += k1 + 3u;
  TF_RND(17) TF_RND(29) TF_RND(16) TF_RND(24)
  v0 += k1;  v1 += ks2 + 4u;
  TF_RND(13) TF_RND(15) TF_RND(26) TF_RND(6)
  v0 += ks2; v1 += k0 + 5u;
#undef TF_RND
#undef TF_ROTL
  o0 = v0; o1 = v1;
}

// ---------------- weight transpose (tiny, once per launch) ----------------
__global__ void nca_prep(const float* __restrict__ w1, const float* __restrict__ w2)
{
  int i = blockIdx.x * 256 + threadIdx.x;
  if (i < KTOT * HID) { int o = i / KTOT, k = i % KTOT; g_w1t[k * HID + o] = w1[i]; }
  if (i < CCH * HID)  { int c = i / HID,  o = i % HID;  g_w2t[o * CCH + c] = w2[i]; }
}

// ---------------- shared memory layout (in floats) ----------------
// sx   [10][10][48]  : 0     .. 4800     halo x tile (reflect-padded)
// sf   [2][48][9]    : 4800  .. 5664     filters (reused as sfire[64] later)
// sb1  [256]         : 5664  .. 5920
// sp   [144][64]     : 5920  .. 15136    perception, k-major
// sh   [256][64]     : 15136 .. 31520    hidden, o-major
// sw   [16][256]     : 31520 .. 35616    w1 k-chunk [k][o]  (reused as w2 chunk [64][48])
#define SM_FLOATS 35616
#define SMEM_BYTES (SM_FLOATS * sizeof(float))

__global__ void __launch_bounds__(256, 1)
nca_step(const float* __restrict__ xin, float* __restrict__ xout,
         const float* __restrict__ filt0, const float* __restrict__ filt1,
         const float* __restrict__ b1g, uint32_t key0, uint32_t key1)
{
  extern __shared__ float sm[];
  float* sx    = sm;
  float* sf    = sm + 4800;
  float* sb1   = sm + 5664;
  float* sp    = sm + 5920;
  float* sh    = sm + 15136;
  float* sw    = sm + 31520;
  float* sfire = sf;             // reused after conv phase

  const int tid = threadIdx.x;
  const int b   = blockIdx.z;
  const int y0  = blockIdx.y * 8;
  const int x0c = blockIdx.x * 8;

  // ---- load filters + bias ----
  for (int i = tid; i < 864; i += 256) sf[i] = (i < 432) ? filt0[i] : filt1[i - 432];
  sb1[tid] = b1g[tid];

  // ---- load 10x10 halo tile with reflect padding ----
  const float* xb = xin + (size_t)b * HWD * HWD * CCH;
  for (int i = tid; i < 4800; i += 256) {
    int c = i % 48; int t2 = i / 48; int hx = t2 % 10; int hy = t2 / 10;
    int gy = y0 - 1 + hy;  gy = (gy < 0) ? -gy : ((gy >= HWD) ? (2 * HWD - 2 - gy) : gy);
    int gx = x0c - 1 + hx; gx = (gx < 0) ? -gx : ((gx >= HWD) ? (2 * HWD - 2 - gx) : gx);
    sx[i] = xb[((size_t)gy * HWD + gx) * CCH + c];
  }
  __syncthreads();

  // ---- perception: sp[k][pix]; k<48: x, 48..95: conv0, 96..143: conv1 ----
  for (int i = tid; i < 48 * 64; i += 256) {
    int k = i >> 6, pix = i & 63, py = pix >> 3, px = pix & 7;
    sp[k * 64 + pix] = sx[((py + 1) * 10 + px + 1) * 48 + k];
  }
  for (int i = tid; i < 2 * 48 * 64; i += 256) {
    int f = i / 3072, r = i % 3072;
    int k = r >> 6, pix = r & 63, py = pix >> 3, px = pix & 7;
    const float* w = sf + f * 432 + k * 9;
    float acc = 0.f;
    #pragma unroll
    for (int dy = 0; dy < 3; dy++)
      #pragma unroll
      for (int dx = 0; dx < 3; dx++)
        acc = fmaf(sx[((py + dy) * 10 + px + dx) * 48 + k], w[dy * 3 + dx], acc);
    sp[(48 + f * 48 + k) * 64 + pix] = acc;
  }

  // ---- GEMM1: h[pix][o] = leakyrelu(sum_k p[pix][k] * w1[o][k] + b1[o]) ----
  // thread t: og = t&15 -> o in {og*4 + 64j + m}, pg = t>>4 -> pixels pg*4..pg*4+3
  const int og = tid & 15, pg = tid >> 4;

  unsigned long long a1[8][4];   // [o-pair][pix], f32x2 lanes = (o, o+1)
  #pragma unroll
  for (int i = 0; i < 8; i++)
    #pragma unroll
    for (int p = 0; p < 4; p++) a1[i][p] = 0ull;

  for (int kc = 0; kc < 9; kc++) {
    __syncthreads();
    for (int i = tid; i < 4096; i += 256) {          // stage w1t chunk [16k][256o]
      int kk = i >> 8, o = i & 255;
      sw[kk * 256 + o] = g_w1t[(kc * 16 + kk) * 256 + o];
    }
    __syncthreads();
    #pragma unroll
    for (int kk = 0; kk < 16; kk++) {
      float4 spv = *(const float4*)&sp[(kc * 16 + kk) * 64 + pg * 4];
      unsigned long long s[4];
      asm("mov.b64 %0,{%1,%1};" : "=l"(s[0]) : "r"(__float_as_uint(spv.x)));
      asm("mov.b64 %0,{%1,%1};" : "=l"(s[1]) : "r"(__float_as_uint(spv.y)));
      asm("mov.b64 %0,{%1,%1};" : "=l"(s[2]) : "r"(__float_as_uint(spv.z)));
      asm("mov.b64 %0,{%1,%1};" : "=l"(s[3]) : "r"(__float_as_uint(spv.w)));
      #pragma unroll
      for (int j = 0; j < 4; j++) {
        // conflict-free: lanes og=0..15 hit consecutive 16B chunks
        ulonglong2 wv = *(const ulonglong2*)&sw[kk * 256 + og * 4 + j * 64];
        #pragma unroll
        for (int p = 0; p < 4; p++) {
          asm("fma.rn.f32x2 %0, %1, %2, %0;" : "+l"(a1[j*2  ][p]) : "l"(wv.x), "l"(s[p]));
          asm("fma.rn.f32x2 %0, %1, %2, %0;" : "+l"(a1[j*2+1][p]) : "l"(wv.y), "l"(s[p]));
        }
      }
    }
  }

  // ---- bias + leaky relu -> sh[o][pix] ----
  #pragma unroll
  for (int j = 0; j < 4; j++) {
    int ob = og * 4 + j * 64;
    #pragma unroll
    for (int q = 0; q < 2; q++) {
      #pragma unroll
      for (int p = 0; p < 4; p++) {
        unsigned long long v = a1[j*2+q][p];
        float v0 = __uint_as_float((uint32_t)v)         + sb1[ob + q*2];
        float v1 = __uint_as_float((uint32_t)(v >> 32)) + sb1[ob + q*2 + 1];
        v0 = (v0 > 0.f) ? v0 : 0.01f * v0;
        v1 = (v1 > 0.f) ? v1 : 0.01f * v1;
        sh[(ob + q*2    ) * 64 + pg*4 + p] = v0;
        sh[(ob + q*2 + 1) * 64 + pg*4 + p] = v1;
      }
    }
  }

  // ---- fire mask (JAX threefry, partitionable mode: bits = h0 ^ h1 of tf(key,0,n)) ----
  if (tid < 64) {
    int py = tid >> 3, px = tid & 7;
    uint32_t n = ((uint32_t)b * HWD + (uint32_t)(y0 + py)) * HWD + (uint32_t)(x0c + px);
    uint32_t r0, r1;
    threefry2x32(key0, key1, 0u, n, r0, r1);
    uint32_t bits = r0 ^ r1;
    float u = __uint_as_float((bits >> 9) | 0x3f800000u) - 1.0f;
    sfire[tid] = (u > 0.5f) ? 1.0f : 0.0f;
  }

  // ---- GEMM2: d[pix][c] = sum_o h[pix][o] * w2[c][o]  (w2t in smem, 4 o-chunks) ----
  const int co = og;                       // c in {co*3 .. co*3+2}
  unsigned long long a2[3][2];             // [c][pix-pair], lanes = (pix, pix+1)
  #pragma unroll
  for (int cc = 0; cc < 3; cc++) { a2[cc][0] = 0ull; a2[cc][1] = 0ull; }

  for (int oc = 0; oc < 4; oc++) {
    __syncthreads();                       // also publishes sh / sfire on first pass
    for (int i = tid; i < 3072; i += 256) sw[i] = g_w2t[oc * 3072 + i];  // [64 o][48 c]
    __syncthreads();
    #pragma unroll 8
    for (int oo = 0; oo < 64; oo++) {
      int o = oc * 64 + oo;
      ulonglong2 hv = *(const ulonglong2*)&sh[o * 64 + pg * 4];
      #pragma unroll
      for (int cc = 0; cc < 3; cc++) {
        unsigned long long wd;
        asm("mov.b64 %0,{%1,%1};" : "=l"(wd) : "r"(__float_as_uint(sw[oo * 48 + co * 3 + cc])));
        asm("fma.rn.f32x2 %0, %1, %2, %0;" : "+l"(a2[cc][0]) : "l"(wd), "l"(hv.x));
        asm("fma.rn.f32x2 %0, %1, %2, %0;" : "+l"(a2[cc][1]) : "l"(wd), "l"(hv.y));
      }
    }
  }

  // ---- masked residual update: x_out = x + fire * chmask * d ----
  float* xob = xout + (size_t)b * HWD * HWD * CCH;
  #pragma unroll
  for (int p = 0; p < 4; p++) {
    int pix = pg * 4 + p, py = pix >> 3, px = pix & 7;
    size_t base = ((size_t)(y0 + py) * HWD + (x0c + px)) * CCH;
    float fire = sfire[pix];
    #pragma unroll
    for (int cc = 0; cc < 3; cc++) {
      int c = co * 3 + cc;
      unsigned long long v = a2[cc][p >> 1];
      float d = (p & 1) ? __uint_as_float((uint32_t)(v >> 32)) : __uint_as_float((uint32_t)v);
      float xold = sx[((py + 1) * 10 + px + 1) * 48 + c];
      xob[base + c] = xold + ((c >= 3) ? fire * d : 0.f);
    }
  }
}

// ---------------- launcher ----------------
extern "C" void kernel_launch(void* const* d_in, const int* in_sizes, int n_in,
                              void* d_out, int out_size)
{
  const float* x     = (const float*)d_in[0];
  const float* filt0 = (const float*)d_in[1];
  const float* filt1 = (const float*)d_in[2];
  const float* w1    = (const float*)d_in[3];
  const float* b1    = (const float*)d_in[4];
  const float* w2    = (const float*)d_in[5];
  // d_in[6] = steps (fixed at 4 for this problem)

  float* xbuf = nullptr;
  cudaGetSymbolAddress((void**)&xbuf, g_xbuf);
  float* outp = (float*)d_out;

  cudaFuncSetAttribute(nca_step, cudaFuncAttributeMaxDynamicSharedMemorySize,
                       (int)SMEM_BYTES);

  nca_prep<<<144, 256>>>(w1, w2);

  dim3 grid(32, 32, 8), blk(256);
  const float* src = x;
  for (int i = 0; i < 4; i++) {
    // key_i = fold_in(key(42), i) ; k1 = split(key_i)[0]  (partitionable threefry)
    uint32_t f0, f1; threefry2x32(0u, 42u, 0u, (uint32_t)i, f0, f1);
    uint32_t a0, a1; threefry2x32(f0, f1, 0u, 0u, a0, a1);
    float* dst = (i % 2 == 0) ? xbuf : outp;
    nca_step<<<grid, blk, SMEM_BYTES>>>(src, dst, filt0, filt1, b1, a0, a1);
    src = dst;
  }
}

// round 2
// speedup vs baseline: 2.5066x; 2.5066x over previous
#include <cuda_runtime.h>
#include <cstdint>

// ---------------- constants ----------------
#define CCH   48
#define HID   256
#define HWD   256
#define BN    8
#define KTOT  144

// ---------------- device scratch ----------------
__device__ float g_xbuf[(size_t)BN * HWD * HWD * CCH];   // ping-pong x buffer
__device__ float g_w1t[KTOT * HID];                      // w1 transposed: [k][o]
__device__ float g_w2t[HID * CCH];                       // w2 transposed: [o][c]

// ---------------- threefry2x32 (exact JAX semantics, 20 rounds) ----------------
__host__ __device__ __forceinline__ void threefry2x32(
    uint32_t k0, uint32_t k1, uint32_t x0, uint32_t x1,
    uint32_t& o0, uint32_t& o1)
{
  uint32_t ks2 = k0 ^ k1 ^ 0x1BD11BDAu;
  uint32_t v0 = x0 + k0, v1 = x1 + k1;
#define TF_ROTL(v, r) (((v) << (r)) | ((v) >> (32 - (r))))
#define TF_RND(r) { v0 += v1; v1 = TF_ROTL(v1, r); v1 ^= v0; }
  TF_RND(13) TF_RND(15) TF_RND(26) TF_RND(6)
  v0 += k1;  v1 += ks2 + 1u;
  TF_RND(17) TF_RND(29) TF_RND(16) TF_RND(24)
  v0 += ks2; v1 += k0 + 2u;
  TF_RND(13) TF_RND(15) TF_RND(26) TF_RND(6)
  v0 += k0;  v1 += k1 + 3u;
  TF_RND(17) TF_RND(29) TF_RND(16) TF_RND(24)
  v0 += k1;  v1 += ks2 + 4u;
  TF_RND(13) TF_RND(15) TF_RND(26) TF_RND(6)
  v0 += ks2; v1 += k0 + 5u;
#undef TF_RND
#undef TF_ROTL
  o0 = v0; o1 = v1;
}

// ---------------- weight transpose ----------------
__global__ void nca_prep(const float* __restrict__ w1, const float* __restrict__ w2)
{
  int i = blockIdx.x * 256 + threadIdx.x;
  if (i < KTOT * HID) { int o = i / KTOT, k = i % KTOT; g_w1t[k * HID + o] = w1[i]; }
  if (i < CCH * HID)  { int c = i / HID,  o = i % HID;  g_w2t[o * CCH + c] = w2[i]; }
}

// ---------------- shared memory layout (floats) ----------------
// sx   [10][10][48]     : 0     .. 4800
// sf   [2][48][9]       : 4800  .. 5664    (reused as sfire[64])
// sb1  [256]            : 5664  .. 5920
// spsh                  : 5920  .. 22304   sp[144][64] (first 9216) / sh[256][64] alias
// sw                    : 22304 .. 26400   w1 chunk [16][256] / w2 chunk [64][48]
#define SM_FLOATS 26400
#define SMEM_BYTES (SM_FLOATS * sizeof(float))

// swizzled column for sp/sh: rotate 4-float groups by (row & 60), keep low 2 bits
#define SWC(K, pix) (((((pix) & 60) + ((K) & 60)) & 63) + ((pix) & 3))

__global__ void __launch_bounds__(256, 2)
nca_step(const float* __restrict__ xin, float* __restrict__ xout,
         const float* __restrict__ filt0, const float* __restrict__ filt1,
         const float* __restrict__ b1g, uint32_t key0, uint32_t key1)
{
  extern __shared__ float sm[];
  float* sx    = sm;
  float* sf    = sm + 4800;
  float* sb1   = sm + 5664;
  float* sp    = sm + 5920;
  float* sh    = sm + 5920;     // alias: sp dead once GEMM1 accs are in regs
  float* sw    = sm + 22304;
  float* sfire = sf;            // alias: filters dead after conv

  const int tid = threadIdx.x;
  const int b   = blockIdx.z;
  const int y0  = blockIdx.y * 8;
  const int x0c = blockIdx.x * 8;

  // ---- filters + bias ----
  for (int i = tid; i < 864; i += 256) sf[i] = (i < 432) ? filt0[i] : filt1[i - 432];
  sb1[tid] = b1g[tid];

  // ---- 10x10 halo tile, reflect padding, vectorized float4 ----
  const float* xb = xin + (size_t)b * HWD * HWD * CCH;
  for (int i = tid; i < 1200; i += 256) {
    int c4 = i % 12; int t2 = i / 12; int hx = t2 % 10; int hy = t2 / 10;
    int gy = y0 - 1 + hy;  gy = (gy < 0) ? -gy : ((gy >= HWD) ? (2 * HWD - 2 - gy) : gy);
    int gx = x0c - 1 + hx; gx = (gx < 0) ? -gx : ((gx >= HWD) ? (2 * HWD - 2 - gx) : gx);
    ((float4*)sx)[i] = *(const float4*)&xb[((size_t)gy * HWD + gx) * CCH + c4 * 4];
  }
  __syncthreads();

  // ---- perception into sp (k-fast lane mapping: conflict-free sx reads) ----
  for (int i = tid; i < 48 * 64; i += 256) {
    int k = i % 48, pix = i / 48, py = pix >> 3, px = pix & 7;
    sp[k * 64 + SWC(k, pix)] = sx[((py + 1) * 10 + px + 1) * 48 + k];
  }
  for (int i = tid; i < 6144; i += 256) {
    int k = i % 48, f = (i / 48) & 1, pix = i / 96, py = pix >> 3, px = pix & 7;
    const float* w = sf + f * 432 + k * 9;
    float acc = 0.f;
    #pragma unroll
    for (int dy = 0; dy < 3; dy++)
      #pragma unroll
      for (int dx = 0; dx < 3; dx++)
        acc = fmaf(sx[((py + dy) * 10 + px + dx) * 48 + k], w[dy * 3 + dx], acc);
    int K = 48 + f * 48 + k;
    sp[K * 64 + SWC(K, pix)] = acc;
  }

  // ---- GEMM1: h[pix][o], thread = (og: 16 o's, pg: 4 pixels) ----
  const int og = tid & 15, pg = tid >> 4;

  unsigned long long a1[8][4];
  #pragma unroll
  for (int i = 0; i < 8; i++)
    #pragma unroll
    for (int p = 0; p < 4; p++) a1[i][p] = 0ull;

  // register double-buffer of w1 chunks (16 k rows = 4096 floats = 4 float4/thread)
  float4 pre1[4];
  #pragma unroll
  for (int q = 0; q < 4; q++) pre1[q] = ((const float4*)g_w1t)[tid + 256 * q];

  for (int kc = 0; kc < 9; kc++) {
    __syncthreads();                         // prev chunk fully consumed
    #pragma unroll
    for (int q = 0; q < 4; q++) ((float4*)sw)[tid + 256 * q] = pre1[q];
    if (kc < 8) {
      #pragma unroll
      for (int q = 0; q < 4; q++)
        pre1[q] = ((const float4*)(g_w1t + (kc + 1) * 4096))[tid + 256 * q];
    }
    __syncthreads();                         // chunk visible
    #pragma unroll
    for (int kk = 0; kk < 16; kk++) {
      int K = kc * 16 + kk;
      float4 spv = *(const float4*)&sp[K * 64 + (((pg * 4) + (K & 60)) & 63)];
      unsigned long long s[4];
      asm("mov.b64 %0,{%1,%1};" : "=l"(s[0]) : "r"(__float_as_uint(spv.x)));
      asm("mov.b64 %0,{%1,%1};" : "=l"(s[1]) : "r"(__float_as_uint(spv.y)));
      asm("mov.b64 %0,{%1,%1};" : "=l"(s[2]) : "r"(__float_as_uint(spv.z)));
      asm("mov.b64 %0,{%1,%1};" : "=l"(s[3]) : "r"(__float_as_uint(spv.w)));
      #pragma unroll
      for (int j = 0; j < 4; j++) {
        ulonglong2 wv = *(const ulonglong2*)&sw[kk * 256 + og * 4 + j * 64];
        #pragma unroll
        for (int p = 0; p < 4; p++) {
          asm("fma.rn.f32x2 %0, %1, %2, %0;" : "+l"(a1[j*2  ][p]) : "l"(wv.x), "l"(s[p]));
          asm("fma.rn.f32x2 %0, %1, %2, %0;" : "+l"(a1[j*2+1][p]) : "l"(wv.y), "l"(s[p]));
        }
      }
    }
  }

  // prefetch first w2 chunk (64 o rows = 3072 floats = 3 float4/thread)
  float4 pre2[3];
  #pragma unroll
  for (int q = 0; q < 3; q++) pre2[q] = ((const float4*)g_w2t)[tid + 256 * q];

  __syncthreads();   // all sp reads done before sh (aliased) writes

  // ---- epilogue: bias + leaky relu -> sh[o][pix] (swizzled, float4 stores) ----
  #pragma unroll
  for (int j = 0; j < 4; j++)
    #pragma unroll
    for (int q = 0; q < 2; q++)
      #pragma unroll
      for (int l = 0; l < 2; l++) {
        int o = og * 4 + j * 64 + q * 2 + l;
        float bias = sb1[o];
        float4 v;
        float* vp = &v.x;
        #pragma unroll
        for (int p = 0; p < 4; p++) {
          unsigned long long u = a1[j * 2 + q][p];
          float f = l ? __uint_as_float((uint32_t)(u >> 32))
                      : __uint_as_float((uint32_t)u);
          f += bias;
          f = (f > 0.f) ? f : 0.01f * f;
          vp[p] = f;
        }
        *(float4*)&sh[o * 64 + (((pg * 4) + (o & 60)) & 63)] = v;
      }

  // ---- fire mask (JAX threefry, partitionable: bits = h0^h1 of tf(key,0,n)) ----
  if (tid < 64) {
    int py = tid >> 3, px = tid & 7;
    uint32_t n = ((uint32_t)b * HWD + (uint32_t)(y0 + py)) * HWD + (uint32_t)(x0c + px);
    uint32_t r0, r1;
    threefry2x32(key0, key1, 0u, n, r0, r1);
    uint32_t bits = r0 ^ r1;
    float u = __uint_as_float((bits >> 9) | 0x3f800000u) - 1.0f;
    sfire[tid] = (u > 0.5f) ? 1.0f : 0.0f;
  }

  // ---- GEMM2: d[pix][c] = sum_o h[o][pix] * w2t[o][c], thread = (co: 3 c's, pg: 4 pix) ----
  const int co = og;
  unsigned long long a2[3][2];
  #pragma unroll
  for (int cc = 0; cc < 3; cc++) { a2[cc][0] = 0ull; a2[cc][1] = 0ull; }

  for (int oc = 0; oc < 4; oc++) {
    __syncthreads();                         // publishes sh/sfire (1st) & guards sw
    #pragma unroll
    for (int q = 0; q < 3; q++) ((float4*)sw)[tid + 256 * q] = pre2[q];
    if (oc < 3) {
      #pragma unroll
      for (int q = 0; q < 3; q++)
        pre2[q] = ((const float4*)(g_w2t + (oc + 1) * 3072))[tid + 256 * q];
    }
    __syncthreads();
    #pragma unroll 8
    for (int oo = 0; oo < 64; oo++) {
      int o = oc * 64 + oo;
      ulonglong2 hv = *(const ulonglong2*)&sh[o * 64 + (((pg * 4) + (o & 60)) & 63)];
      #pragma unroll
      for (int cc = 0; cc < 3; cc++) {
        unsigned long long wd;
        asm("mov.b64 %0,{%1,%1};" : "=l"(wd) : "r"(__float_as_uint(sw[oo * 48 + co * 3 + cc])));
        asm("fma.rn.f32x2 %0, %1, %2, %0;" : "+l"(a2[cc][0]) : "l"(wd), "l"(hv.x));
        asm("fma.rn.f32x2 %0, %1, %2, %0;" : "+l"(a2[cc][1]) : "l"(wd), "l"(hv.y));
      }
    }
  }

  // ---- masked residual update ----
  float* xob = xout + (size_t)b * HWD * HWD * CCH;
  #pragma unroll
  for (int p = 0; p < 4; p++) {
    int pix = pg * 4 + p, py = pix >> 3, px = pix & 7;
    size_t base = ((size_t)(y0 + py) * HWD + (x0c + px)) * CCH;
    float fire = sfire[pix];
    #pragma unroll
    for (int cc = 0; cc < 3; cc++) {
      int c = co * 3 + cc;
      unsigned long long v = a2[cc][p >> 1];
      float d = (p & 1) ? __uint_as_float((uint32_t)(v >> 32)) : __uint_as_float((uint32_t)v);
      float xold = sx[((py + 1) * 10 + px + 1) * 48 + c];
      xob[base + c] = xold + ((c >= 3) ? fire * d : 0.f);
    }
  }
}

// ---------------- launcher ----------------
extern "C" void kernel_launch(void* const* d_in, const int* in_sizes, int n_in,
                              void* d_out, int out_size)
{
  const float* x     = (const float*)d_in[0];
  const float* filt0 = (const float*)d_in[1];
  const float* filt1 = (const float*)d_in[2];
  const float* w1    = (const float*)d_in[3];
  const float* b1    = (const float*)d_in[4];
  const float* w2    = (const float*)d_in[5];

  float* xbuf = nullptr;
  cudaGetSymbolAddress((void**)&xbuf, g_xbuf);
  float* outp = (float*)d_out;

  cudaFuncSetAttribute(nca_step, cudaFuncAttributeMaxDynamicSharedMemorySize,
                       (int)SMEM_BYTES);

  nca_prep<<<144, 256>>>(w1, w2);

  dim3 grid(32, 32, 8), blk(256);
  const float* src = x;
  for (int i = 0; i < 4; i++) {
    uint32_t f0, f1; threefry2x32(0u, 42u, 0u, (uint32_t)i, f0, f1);
    uint32_t a0, a1; threefry2x32(f0, f1, 0u, 0u, a0, a1);
    float* dst = (i % 2 == 0) ? xbuf : outp;
    nca_step<<<grid, blk, SMEM_BYTES>>>(src, dst, filt0, filt1, b1, a0, a1);
    src = dst;
  }
}

// round 4
// speedup vs baseline: 5.9489x; 2.3733x over previous
#include <cuda_runtime.h>
#include <cstdint>

#define HWD 256
#define NTILES 8192      // 8 batches * 32 * 32 tiles of 8x8 pixels

// ---------------- device scratch ----------------
__device__ float g_xbuf[(size_t)8 * HWD * HWD * 48];
__device__ unsigned int g_ctr[4];

// ---------------- threefry2x32 (exact JAX, 20 rounds) ----------------
__host__ __device__ __forceinline__ void threefry2x32(
    uint32_t k0, uint32_t k1, uint32_t x0, uint32_t x1, uint32_t& o0, uint32_t& o1) {
  uint32_t ks2 = k0 ^ k1 ^ 0x1BD11BDAu;
  uint32_t v0 = x0 + k0, v1 = x1 + k1;
#define TF_ROTL(v, r) (((v) << (r)) | ((v) >> (32 - (r))))
#define TF_RND(r) { v0 += v1; v1 = TF_ROTL(v1, r); v1 ^= v0; }
  TF_RND(13) TF_RND(15) TF_RND(26) TF_RND(6)
  v0 += k1;  v1 += ks2 + 1u;
  TF_RND(17) TF_RND(29) TF_RND(16) TF_RND(24)
  v0 += ks2; v1 += k0 + 2u;
  TF_RND(13) TF_RND(15) TF_RND(26) TF_RND(6)
  v0 += k0;  v1 += k1 + 3u;
  TF_RND(17) TF_RND(29) TF_RND(16) TF_RND(24)
  v0 += k1;  v1 += ks2 + 4u;
  TF_RND(13) TF_RND(15) TF_RND(26) TF_RND(6)
  v0 += ks2; v1 += k0 + 5u;
#undef TF_RND
#undef TF_ROTL
  o0 = v0; o1 = v1;
}

__global__ void nca_reset() { if (threadIdx.x < 4) g_ctr[threadIdx.x] = 0u; }

// ---------------- mma helpers (baseline PTX, sm_80+) ----------------
__device__ __forceinline__ uint32_t cvt_tf32(float f) {
  uint32_t r; asm("cvt.rna.tf32.f32 %0, %1;" : "=r"(r) : "f"(f)); return r;
}
__device__ __forceinline__ void mma_tf32(float* c, uint32_t a0, uint32_t a1,
                                         uint32_t a2, uint32_t a3,
                                         uint32_t b0, uint32_t b1) {
  asm volatile(
    "mma.sync.aligned.m16n8k8.row.col.f32.tf32.tf32.f32 "
    "{%0,%1,%2,%3},{%4,%5,%6,%7},{%8,%9},{%0,%1,%2,%3};"
    : "+f"(c[0]), "+f"(c[1]), "+f"(c[2]), "+f"(c[3])
    : "r"(a0), "r"(a1), "r"(a2), "r"(a3), "r"(b0), "r"(b1));
}

// ---------------- shared memory layout (float offsets) ----------------
// ctrl[8] | sfire[64] | sb1[256] | sfilt[864] | shalo[48][102] |
// P[64][164] | H[64][260] | sW2[256][56]
#define F_CTRL  0
#define F_FIRE  8
#define F_B1    72
#define F_FILT  328
#define F_HALO  1192          // 48*102 = 4896
#define F_P     6088          // 64*164 = 10496
#define F_H     16584         // 64*260 = 16640
#define F_W2    33224         // 256*56 = 14336
#define SM_FLOATS 47560
#define SMEM_BYTES (SM_FLOATS * sizeof(float))
#define PST 164               // P stride  (164 % 32 == 4  -> conflict-free frags)
#define HST 260               // H stride  (260 % 32 == 4)
#define WST 56                // W2 stride (56  % 32 == 24 -> conflict-free B frags)
#define HLS 102               // halo plane stride (even for float2)

__global__ void __launch_bounds__(256, 1)
nca_step_mma(const float* __restrict__ xin, float* __restrict__ xout,
             const float* __restrict__ filt0, const float* __restrict__ filt1,
             const float* __restrict__ b1g,
             const float* __restrict__ w1g, const float* __restrict__ w2g,
             uint32_t key0, uint32_t key1, int step)
{
  extern __shared__ float sm[];
  float* sfire = sm + F_FIRE;
  float* sb1   = sm + F_B1;
  float* sfilt = sm + F_FILT;
  float* shalo = sm + F_HALO;
  float* Pb    = sm + F_P;
  float* Hb    = sm + F_H;
  float* sW2   = sm + F_W2;

  const int tid = threadIdx.x;
  const int wid = tid >> 5, lid = tid & 31;
  const int g = lid >> 2, t = lid & 3;

  // ---- per-launch setup ----
  sb1[tid] = b1g[tid];
  for (int i = tid; i < 864; i += 256) sfilt[i] = (i < 432) ? filt0[i] : filt1[i - 432];
  for (int i = tid; i < 12288; i += 256) {          // w2 [48][256] -> sW2[o][c] tf32
    int c = i >> 8, o = i & 255;
    sW2[o * WST + c] = __uint_as_float(cvt_tf32(w2g[i]));
  }

  // W1 B-fragments in registers: warp owns N slice wid*32..wid*32+31
  uint32_t B1[18][4][2];
  #pragma unroll
  for (int ks = 0; ks < 18; ks++)
    #pragma unroll
    for (int nb = 0; nb < 4; nb++) {
      int o = wid * 32 + nb * 8 + g;
      B1[ks][nb][0] = cvt_tf32(w1g[o * 144 + ks * 8 + t]);
      B1[ks][nb][1] = cvt_tf32(w1g[o * 144 + ks * 8 + t + 4]);
    }
  float biasr[4][2];
  #pragma unroll
  for (int nb = 0; nb < 4; nb++) {
    biasr[nb][0] = b1g[wid * 32 + nb * 8 + 2 * t];
    biasr[nb][1] = b1g[wid * 32 + nb * 8 + 2 * t + 1];
  }
  __syncthreads();

  // ---- persistent tile loop ----
  for (;;) {
    if (tid == 0) {
      unsigned tt = atomicAdd(&g_ctr[step], 1u);
      *(volatile unsigned*)(sm + F_CTRL) = tt;
    }
    __syncthreads();
    unsigned tt = *(volatile unsigned*)(sm + F_CTRL);
    if (tt >= NTILES) break;

    const int bb = (int)(tt >> 10);
    const int y0 = (int)((tt >> 5) & 31) * 8;
    const int x0c = (int)(tt & 31) * 8;
    const float* xb = xin + (size_t)bb * HWD * HWD * 48;

    // ---- halo [48][10][10] planar, reflect, float4 gmem reads ----
    for (int i = tid; i < 1200; i += 256) {
      int c4 = i % 12, pos = i / 12, row = pos / 10, col = pos % 10;
      int gy = y0 - 1 + row; gy = (gy < 0) ? -gy : ((gy >= HWD) ? 2 * HWD - 2 - gy : gy);
      int gx = x0c - 1 + col; gx = (gx < 0) ? -gx : ((gx >= HWD) ? 2 * HWD - 2 - gx : gx);
      float4 v = *(const float4*)(xb + ((size_t)gy * HWD + gx) * 48 + c4 * 4);
      shalo[(c4 * 4 + 0) * HLS + pos] = v.x;
      shalo[(c4 * 4 + 1) * HLS + pos] = v.y;
      shalo[(c4 * 4 + 2) * HLS + pos] = v.z;
      shalo[(c4 * 4 + 3) * HLS + pos] = v.w;
    }
    __syncthreads();

    // ---- x-copy: P[pix][k<48] (tf32-rounded) ----
    {
      int pix = tid >> 2, ko = (tid & 3) * 12;
      int py = pix >> 3, px = pix & 7;
      int pos = (py + 1) * 10 + px + 1;
      #pragma unroll
      for (int j = 0; j < 12; j++)
        Pb[pix * PST + ko + j] =
            __uint_as_float(cvt_tf32(shalo[(ko + j) * HLS + pos]));
    }
    // ---- depthwise convs: task = (py, kf), 8 px per thread ----
    #pragma unroll
    for (int it = 0; it < 3; it++) {
      int task = it * 256 + tid;               // < 768 = 8 py * 96 kf
      int py = task / 96, kf = task % 96;
      const float* cf = sfilt + kf * 9;
      const float* plane = shalo + (kf % 48) * HLS;
      float acc[8] = {0.f,0.f,0.f,0.f,0.f,0.f,0.f,0.f};
      #pragma unroll
      for (int dy = 0; dy < 3; dy++) {
        const float* rp = plane + (py + dy) * 10;
        float v[10];
        #pragma unroll
        for (int q = 0; q < 5; q++) { float2 u = *(const float2*)(rp + 2 * q); v[2*q] = u.x; v[2*q+1] = u.y; }
        #pragma unroll
        for (int dx = 0; dx < 3; dx++) {
          float w = cf[dy * 3 + dx];
          #pragma unroll
          for (int i = 0; i < 8; i++) acc[i] = fmaf(v[i + dx], w, acc[i]);
        }
      }
      int K = 48 + kf;
      #pragma unroll
      for (int i = 0; i < 8; i++)
        Pb[(py * 8 + i) * PST + K] = __uint_as_float(cvt_tf32(acc[i]));
    }
    // ---- fire mask ----
    if (tid < 64) {
      int py = tid >> 3, px = tid & 7;
      uint32_t n = ((uint32_t)bb * HWD + (uint32_t)(y0 + py)) * HWD + (uint32_t)(x0c + px);
      uint32_t r0, r1;
      threefry2x32(key0, key1, 0u, n, r0, r1);
      float u = __uint_as_float(((r0 ^ r1) >> 9) | 0x3f800000u) - 1.0f;
      sfire[tid] = (u > 0.5f) ? 1.0f : 0.0f;
    }
    __syncthreads();

    // ---- GEMM1: warp = N slice (32), all 64 px in 2 M-chunks ----
    #pragma unroll
    for (int mc = 0; mc < 2; mc++) {
      float acc[2][4][4];
      #pragma unroll
      for (int mb = 0; mb < 2; mb++)
        #pragma unroll
        for (int nb = 0; nb < 4; nb++)
          #pragma unroll
          for (int e = 0; e < 4; e++) acc[mb][nb][e] = 0.f;

      const float* pr0 = Pb + (mc * 32 + g) * PST + t;
      #pragma unroll
      for (int ks = 0; ks < 18; ks++) {
        uint32_t a[2][4];
        #pragma unroll
        for (int mb = 0; mb < 2; mb++) {
          const float* pr = pr0 + mb * 16 * PST + ks * 8;
          a[mb][0] = __float_as_uint(pr[0]);
          a[mb][1] = __float_as_uint(pr[8 * PST]);
          a[mb][2] = __float_as_uint(pr[4]);
          a[mb][3] = __float_as_uint(pr[8 * PST + 4]);
        }
        #pragma unroll
        for (int nb = 0; nb < 4; nb++)
          #pragma unroll
          for (int mb = 0; mb < 2; mb++)
            mma_tf32(acc[mb][nb], a[mb][0], a[mb][1], a[mb][2], a[mb][3],
                     B1[ks][nb][0], B1[ks][nb][1]);
      }
      // epilogue1: bias + leaky + tf32 -> H
      #pragma unroll
      for (int mb = 0; mb < 2; mb++)
        #pragma unroll
        for (int nb = 0; nb < 4; nb++) {
          int row = mc * 32 + mb * 16 + g;
          int col = wid * 32 + nb * 8 + 2 * t;
          float v0 = acc[mb][nb][0] + biasr[nb][0];
          float v1 = acc[mb][nb][1] + biasr[nb][1];
          v0 = (v0 > 0.f) ? v0 : 0.01f * v0;
          v1 = (v1 > 0.f) ? v1 : 0.01f * v1;
          *(float2*)&Hb[row * HST + col] = make_float2(
              __uint_as_float(cvt_tf32(v0)), __uint_as_float(cvt_tf32(v1)));
          float v2 = acc[mb][nb][2] + biasr[nb][0];
          float v3 = acc[mb][nb][3] + biasr[nb][1];
          v2 = (v2 > 0.f) ? v2 : 0.01f * v2;
          v3 = (v3 > 0.f) ? v3 : 0.01f * v3;
          *(float2*)&Hb[(row + 8) * HST + col] = make_float2(
              __uint_as_float(cvt_tf32(v2)), __uint_as_float(cvt_tf32(v3)));
        }
    }
    __syncthreads();

    // ---- GEMM2: warp = (16 rows, 24 cols), K = 256 ----
    const int mb2 = wid >> 1, nh = wid & 1;
    float acc2[3][4];
    #pragma unroll
    for (int nb = 0; nb < 3; nb++)
      #pragma unroll
      for (int e = 0; e < 4; e++) acc2[nb][e] = 0.f;

    const float* hb = Hb + (mb2 * 16 + g) * HST + t;
    #pragma unroll 4
    for (int ks = 0; ks < 32; ks++) {
      uint32_t a0 = __float_as_uint(hb[ks * 8]);
      uint32_t a1 = __float_as_uint(hb[8 * HST + ks * 8]);
      uint32_t a2 = __float_as_uint(hb[ks * 8 + 4]);
      uint32_t a3 = __float_as_uint(hb[8 * HST + ks * 8 + 4]);
      #pragma unroll
      for (int nb = 0; nb < 3; nb++) {
        int c = nh * 24 + nb * 8 + g;
        uint32_t b0 = __float_as_uint(sW2[(ks * 8 + t) * WST + c]);
        uint32_t b1 = __float_as_uint(sW2[(ks * 8 + t + 4) * WST + c]);
        mma_tf32(acc2[nb], a0, a1, a2, a3, b0, b1);
      }
    }

    // ---- epilogue2: fire + masked residual -> gmem ----
    #pragma unroll
    for (int nb = 0; nb < 3; nb++) {
      int c = nh * 24 + nb * 8 + 2 * t;
      #pragma unroll
      for (int hf = 0; hf < 2; hf++) {
        int pix = mb2 * 16 + g + hf * 8;
        int py = pix >> 3, px = pix & 7;
        float fire = sfire[pix];
        float d0 = acc2[nb][hf * 2 + 0], d1 = acc2[nb][hf * 2 + 1];
        int pos = (py + 1) * 10 + px + 1;
        float xo0 = shalo[c * HLS + pos];
        float xo1 = shalo[(c + 1) * HLS + pos];
        float o0 = xo0 + ((c     >= 3) ? fire * d0 : 0.f);
        float o1 = xo1 + ((c + 1 >= 3) ? fire * d1 : 0.f);
        float* op = xout + (((size_t)bb * HWD + (y0 + py)) * HWD + (x0c + px)) * 48 + c;
        *(float2*)op = make_float2(o0, o1);
      }
    }
    // loop-top __syncthreads orders next-tile smem writes after these reads
  }
}

// ---------------- launcher ----------------
extern "C" void kernel_launch(void* const* d_in, const int* in_sizes, int n_in,
                              void* d_out, int out_size)
{
  const float* x     = (const float*)d_in[0];
  const float* filt0 = (const float*)d_in[1];
  const float* filt1 = (const float*)d_in[2];
  const float* w1    = (const float*)d_in[3];
  const float* b1    = (const float*)d_in[4];
  const float* w2    = (const float*)d_in[5];

  float* xbuf = nullptr;
  cudaGetSymbolAddress((void**)&xbuf, g_xbuf);
  float* outp = (float*)d_out;

  int nsm = 148;
  cudaDeviceGetAttribute(&nsm, cudaDevAttrMultiProcessorCount, 0);

  cudaFuncSetAttribute(nca_step_mma, cudaFuncAttributeMaxDynamicSharedMemorySize,
                       (int)SMEM_BYTES);

  nca_reset<<<1, 32>>>();

  const float* src = x;
  for (int i = 0; i < 4; i++) {
    uint32_t f0, f1; threefry2x32(0u, 42u, 0u, (uint32_t)i, f0, f1);
    uint32_t a0, a1; threefry2x32(f0, f1, 0u, 0u, a0, a1);
    float* dst = (i & 1) ? outp : xbuf;
    if (i == 3) dst = outp;
    nca_step_mma<<<nsm, 256, SMEM_BYTES>>>(src, dst, filt0, filt1, b1, w1, w2,
                                           a0, a1, i);
    src = dst;
  }
}